// round 3
// baseline (speedup 1.0000x reference)
#include <cuda_runtime.h>
#include <math.h>

#define BATCH 4
#define CH    64
#define H     96
#define W     96
#define HD    48          // downsampled H/W
#define LL    2304        // 48*48 patches
#define KC    576         // CH*9
#define PDIM  1024        // CH*16

// ---------------- scratch (device globals; no cudaMalloc allowed) ----------------
__device__ float g_fd[BATCH*CH*HD*HD];
__device__ float g_bd[BATCH*CH*HD*HD];
__device__ float g_G [BATCH*LL*KC];
__device__ float g_F [BATCH*LL*KC];
__device__ float g_inv[BATCH*LL];
__device__ float g_A [BATCH*(size_t)LL*LL];   // score / softmax buffer
__device__ float g_Bf[BATCH*(size_t)LL*LL];   // fuse ping-pong
__device__ float g_R [BATCH*LL*PDIM];
__device__ float g_OC[BATCH*(size_t)PDIM*LL];
__device__ float g_y [BATCH*CH*H*W];
__device__ float g_t [BATCH*CH*H*W];

// ---------------- downsample f,b by 2 ----------------
__global__ void k_downsample(const float* __restrict__ f, const float* __restrict__ b) {
    int idx = blockIdx.x*blockDim.x + threadIdx.x;
    if (idx >= BATCH*CH*HD*HD) return;
    int w = idx % HD, h = (idx/HD)%HD, c = (idx/(HD*HD))%CH, bi = idx/(CH*HD*HD);
    int src = ((bi*CH + c)*H + 2*h)*W + 2*w;
    g_fd[idx] = f[src];
    g_bd[idx] = b[src];
}

// ---------------- build G[l][c*9+ij]: scrambled 3x3 bd patches ----------------
__global__ void k_buildG() {
    int idx = blockIdx.x*blockDim.x + threadIdx.x;
    if (idx >= BATCH*LL*KC) return;
    int k  = idx % KC;
    int l  = (idx / KC) % LL;
    int bi = idx / (KC*LL);
    int c  = k / 9;  int ij = k % 9;  int i = ij/3, j = ij%3;
    int c0 = l / 36;
    int p0 = (l % 36)*64 + c;
    int h0 = p0 / 48, w0 = p0 % 48;
    int hh = h0 + i - 1, ww = w0 + j - 1;
    float v = 0.f;
    if ((unsigned)hh < HD && (unsigned)ww < HD)
        v = g_bd[((bi*CH + c0)*HD + hh)*HD + ww];
    g_G[idx] = v;
}

// ---------------- build F[fp][c*9+ij]: fd im2col (pad 1) ----------------
__global__ void k_buildF() {
    int idx = blockIdx.x*blockDim.x + threadIdx.x;
    if (idx >= BATCH*LL*KC) return;
    int k  = idx % KC;
    int fp = (idx / KC) % LL;
    int bi = idx / (KC*LL);
    int c  = k / 9;  int ij = k % 9;  int i = ij/3, j = ij%3;
    int fh = fp / 48, fw = fp % 48;
    int hh = fh + i - 1, ww = fw + j - 1;
    float v = 0.f;
    if ((unsigned)hh < HD && (unsigned)ww < HD)
        v = g_fd[((bi*CH + c)*HD + hh)*HD + ww];
    g_F[idx] = v;
}

// ---------------- per-row inverse norm of G ----------------
__global__ void k_norm() {
    int l  = blockIdx.x;
    int bi = blockIdx.y;
    const float* row = g_G + ((size_t)bi*LL + l)*KC;
    float s = 0.f;
    for (int k = threadIdx.x; k < KC; k += 128) { float v = row[k]; s += v*v; }
    #pragma unroll
    for (int off = 16; off > 0; off >>= 1) s += __shfl_down_sync(0xffffffffu, s, off);
    __shared__ float red[4];
    if ((threadIdx.x & 31) == 0) red[threadIdx.x >> 5] = s;
    __syncthreads();
    if (threadIdx.x == 0) {
        float t = red[0]+red[1]+red[2]+red[3];
        float n = sqrtf(t);
        g_inv[(size_t)bi*LL + l] = 1.0f / fmaxf(n, 1e-4f);
    }
}

// ---------------- generic fp32 tiled GEMM: C[m,n] = rowScale[m]*sum_k A(k,m)*B(k,n) ----
// TA: A stored row-major [M][K] (lda=K). else [K][M] (lda=M).
// TB: B stored row-major [N][K] (ldb=K). else [K][N] (ldb=N).
template<bool TA, bool TB>
__global__ void __launch_bounds__(256)
k_gemm(const float* __restrict__ A, const float* __restrict__ B, float* __restrict__ C,
       const float* __restrict__ rowScale,
       int M, int N, int K, int lda, int ldb,
       size_t sA, size_t sB, size_t sC, int sScale)
{
    __shared__ float As[16][132];
    __shared__ float Bs[16][132];
    int bz = blockIdx.z;
    A += bz * sA;  B += bz * sB;  C += bz * sC;
    int m0 = blockIdx.y * 128, n0 = blockIdx.x * 128;
    int tid = threadIdx.x;
    int trow = tid >> 4, tcol = tid & 15;

    float acc[8][8];
    #pragma unroll
    for (int i=0;i<8;i++)
        #pragma unroll
        for (int j=0;j<8;j++)
            acc[i][j]=0.f;

    for (int k0 = 0; k0 < K; k0 += 16) {
        if (TA) {
            #pragma unroll
            for (int it=0; it<2; it++) {
                int lin = tid + it*256;
                int row = lin >> 2, kq = lin & 3;
                float4 v = *(const float4*)&A[(size_t)(m0+row)*lda + k0 + kq*4];
                As[kq*4+0][row]=v.x; As[kq*4+1][row]=v.y; As[kq*4+2][row]=v.z; As[kq*4+3][row]=v.w;
            }
        } else {
            #pragma unroll
            for (int it=0; it<2; it++) {
                int lin = tid + it*256;
                int kk = lin >> 5, mq = lin & 31;
                float4 v = *(const float4*)&A[(size_t)(k0+kk)*lda + m0 + mq*4];
                *(float4*)&As[kk][mq*4] = v;
            }
        }
        if (TB) {
            #pragma unroll
            for (int it=0; it<2; it++) {
                int lin = tid + it*256;
                int row = lin >> 2, kq = lin & 3;
                float4 v = *(const float4*)&B[(size_t)(n0+row)*ldb + k0 + kq*4];
                Bs[kq*4+0][row]=v.x; Bs[kq*4+1][row]=v.y; Bs[kq*4+2][row]=v.z; Bs[kq*4+3][row]=v.w;
            }
        } else {
            #pragma unroll
            for (int it=0; it<2; it++) {
                int lin = tid + it*256;
                int kk = lin >> 5, nq = lin & 31;
                float4 v = *(const float4*)&B[(size_t)(k0+kk)*ldb + n0 + nq*4];
                *(float4*)&Bs[kk][nq*4] = v;
            }
        }
        __syncthreads();
        #pragma unroll
        for (int k=0;k<16;k++) {
            float a[8], bb[8];
            *(float4*)&a[0]  = *(const float4*)&As[k][trow*8];
            *(float4*)&a[4]  = *(const float4*)&As[k][trow*8+4];
            *(float4*)&bb[0] = *(const float4*)&Bs[k][tcol*8];
            *(float4*)&bb[4] = *(const float4*)&Bs[k][tcol*8+4];
            #pragma unroll
            for (int i=0;i<8;i++)
                #pragma unroll
                for (int j=0;j<8;j++)
                    acc[i][j] += a[i]*bb[j];
        }
        __syncthreads();
    }

    #pragma unroll
    for (int i=0;i<8;i++) {
        int m = m0 + trow*8 + i;
        float sc = rowScale ? rowScale[(size_t)sScale*bz + m] : 1.0f;
        float4 o0, o1;
        o0.x=acc[i][0]*sc; o0.y=acc[i][1]*sc; o0.z=acc[i][2]*sc; o0.w=acc[i][3]*sc;
        o1.x=acc[i][4]*sc; o1.y=acc[i][5]*sc; o1.z=acc[i][6]*sc; o1.w=acc[i][7]*sc;
        *(float4*)&C[(size_t)m*N + n0 + tcol*8]     = o0;
        *(float4*)&C[(size_t)m*N + n0 + tcol*8 + 4] = o1;
    }
}

// ---------------- fuse pass 1: diagonal 3-tap on flat (l, fp) ----------------
__global__ void k_fuse1() {
    size_t idx = (size_t)blockIdx.x*blockDim.x + threadIdx.x;
    if (idx >= (size_t)BATCH*LL*LL) return;
    int fp = (int)(idx % LL);
    int l  = (int)((idx / LL) % LL);
    int bi = (int)(idx / ((size_t)LL*LL));
    const float* src = g_A + (size_t)bi*LL*LL;
    float s = 0.f;
    #pragma unroll
    for (int d=-1; d<=1; d++) {
        int l2 = l+d, f2 = fp+d;
        if ((unsigned)l2 < LL && (unsigned)f2 < LL)
            s += src[(size_t)l2*LL + f2];
    }
    g_Bf[idx] = s;
}

// ---------------- fuse pass 2: diagonal 3-tap on transposed flat indices ----------------
__global__ void k_fuse2() {
    size_t idx = (size_t)blockIdx.x*blockDim.x + threadIdx.x;
    if (idx >= (size_t)BATCH*LL*LL) return;
    int fp = (int)(idx % LL);
    int l  = (int)((idx / LL) % LL);
    int bi = (int)(idx / ((size_t)LL*LL));
    const float* src = g_Bf + (size_t)bi*LL*LL;
    int r = (l  % 48)*48 + l /48;
    int q = (fp % 48)*48 + fp/48;
    float s = 0.f;
    #pragma unroll
    for (int d=-1; d<=1; d++) {
        int r2 = r+d, q2 = q+d;
        if ((unsigned)r2 < LL && (unsigned)q2 < LL) {
            int l2 = (r2 % 48)*48 + r2/48;
            int f2 = (q2 % 48)*48 + q2/48;
            s += src[(size_t)l2*LL + f2];
        }
    }
    g_A[idx] = s;
}

// ---------------- column softmax over l (axis of size 2304), scale 10, in-place g_A ----
__global__ void k_softmax() {
    int bi = blockIdx.y;
    int fp = blockIdx.x*256 + threadIdx.x;
    float* base = g_A + (size_t)bi*LL*LL + fp;
    float mx = -1e30f;
    for (int l=0; l<LL; l++) mx = fmaxf(mx, base[(size_t)l*LL]);
    float sum = 0.f;
    for (int l=0; l<LL; l++) sum += expf(10.0f*(base[(size_t)l*LL]-mx));
    float inv = 1.0f/sum;
    for (int l=0; l<LL; l++) {
        float v = expf(10.0f*(base[(size_t)l*LL]-mx))*inv;
        base[(size_t)l*LL] = v;
    }
}

// ---------------- build R[l][o*16+i*4+j]: scrambled 4x4 stride-2 raw b patches ----------
__global__ void k_buildR(const float* __restrict__ bfull) {
    int idx = blockIdx.x*blockDim.x + threadIdx.x;
    if (idx >= BATCH*LL*PDIM) return;
    int p  = idx % PDIM;
    int l  = (idx / PDIM) % LL;
    int bi = idx / (PDIM*LL);
    int o  = p >> 4;  int ij = p & 15;  int i = ij >> 2, j = ij & 3;
    int c0 = l / 36;
    int p0 = (l % 36)*64 + o;
    int h0 = p0 / 48, w0 = p0 % 48;
    int hy = 2*h0 + i - 1, hx = 2*w0 + j - 1;
    float v = 0.f;
    if ((unsigned)hy < H && (unsigned)hx < W)
        v = bfull[((bi*CH + c0)*H + hy)*W + hx];
    g_R[idx] = v;
}

// ---------------- col2im of deconv (stride 2, kernel 4, pad 2), /4 ----------------
__global__ void k_col2im() {
    int idx = blockIdx.x*blockDim.x + threadIdx.x;
    if (idx >= BATCH*CH*H*W) return;
    int x  = idx % W;
    int y  = (idx / W) % H;
    int o  = (idx / (H*W)) % CH;
    int bi = idx / (CH*H*W);
    const float* OC = g_OC + (size_t)bi*PDIM*LL;
    float s = 0.f;
    int i0 = (y+1)&1, j0 = (x+1)&1;
    #pragma unroll
    for (int di=0; di<2; di++) {
        int i = i0 + 2*di;
        int a = (y+1-i)/2;
        if ((unsigned)a >= 48u) continue;
        #pragma unroll
        for (int dj=0; dj<2; dj++) {
            int j = j0 + 2*dj;
            int bb = (x+1-j)/2;
            if ((unsigned)bb >= 48u) continue;
            s += OC[(size_t)(o*16 + i*4 + j)*LL + a*48 + bb];
        }
    }
    g_y[idx] = 0.25f*s;
}

// ---------------- direct 3x3 conv, 64->64, pad 1, + bias ----------------
__global__ void __launch_bounds__(256)
k_conv3x3(const float* __restrict__ in, const float* __restrict__ wgt,
          const float* __restrict__ bias, float* __restrict__ out)
{
    int bi = blockIdx.z >> 3, og = blockIdx.z & 7;
    int x0 = blockIdx.x * 16, y0 = blockIdx.y * 16;
    int tid = threadIdx.x;
    int tx = tid & 15, ty = tid >> 4;
    __shared__ float sIn[8][18][18];
    __shared__ float sW[8][9][8];   // [c][ij][o]
    float acc[8];
    #pragma unroll
    for (int o=0;o<8;o++) acc[o]=0.f;

    for (int cb = 0; cb < CH; cb += 8) {
        for (int lin = tid; lin < 8*18*18; lin += 256) {
            int c = lin / 324; int rem = lin % 324;
            int iy = rem / 18, ix = rem % 18;
            int gy = y0 + iy - 1, gx = x0 + ix - 1;
            float v = 0.f;
            if ((unsigned)gy < H && (unsigned)gx < W)
                v = in[(((size_t)bi*CH + cb + c)*H + gy)*W + gx];
            sIn[c][iy][ix] = v;
        }
        for (int lin = tid; lin < 576; lin += 256) {
            int c = lin / 72; int rem = lin % 72;
            int ij = rem / 8, o = rem % 8;
            sW[c][ij][o] = wgt[((og*8+o)*CH + cb + c)*9 + ij];
        }
        __syncthreads();
        #pragma unroll
        for (int c=0;c<8;c++)
            #pragma unroll
            for (int dy=0;dy<3;dy++)
                #pragma unroll
                for (int dx=0;dx<3;dx++) {
                    float v = sIn[c][ty+dy][tx+dx];
                    const float* wp = &sW[c][dy*3+dx][0];
                    #pragma unroll
                    for (int o=0;o<8;o++) acc[o] += v * wp[o];
                }
        __syncthreads();
    }
    #pragma unroll
    for (int o=0;o<8;o++)
        out[(((size_t)bi*CH + og*8 + o)*H + y0+ty)*W + x0+tx] = acc[o] + bias[og*8+o];
}

// ---------------- host launcher ----------------
extern "C" void kernel_launch(void* const* d_in, const int* in_sizes, int n_in,
                              void* d_out, int out_size) {
    const float* f  = (const float*)d_in[0];
    const float* b  = (const float*)d_in[1];
    const float* w1 = (const float*)d_in[2];
    const float* b1 = (const float*)d_in[3];
    const float* w2 = (const float*)d_in[4];
    const float* b2 = (const float*)d_in[5];
    float* out = (float*)d_out;

    float *pG, *pF, *pInv, *pA, *pR, *pOC, *pY, *pT;
    cudaGetSymbolAddress((void**)&pG,   g_G);
    cudaGetSymbolAddress((void**)&pF,   g_F);
    cudaGetSymbolAddress((void**)&pInv, g_inv);
    cudaGetSymbolAddress((void**)&pA,   g_A);
    cudaGetSymbolAddress((void**)&pR,   g_R);
    cudaGetSymbolAddress((void**)&pOC,  g_OC);
    cudaGetSymbolAddress((void**)&pY,   g_y);
    cudaGetSymbolAddress((void**)&pT,   g_t);

    // 1. downsample
    k_downsample<<<(BATCH*CH*HD*HD + 255)/256, 256>>>(f, b);
    // 2-3. build matrices
    k_buildG<<<(BATCH*LL*KC + 255)/256, 256>>>();
    k_buildF<<<(BATCH*LL*KC + 255)/256, 256>>>();
    // 4. norms
    k_norm<<<dim3(LL, BATCH), 128>>>();
    // 5. correlation GEMM:  g_A = invnorm * (G @ F^T)   [2304 x 2304, K=576]
    k_gemm<true,true><<<dim3(LL/128, LL/128, BATCH), 256>>>(
        pG, pF, pA, pInv,
        LL, LL, KC, KC, KC,
        (size_t)LL*KC, (size_t)LL*KC, (size_t)LL*LL, LL);
    // 6-7. fuse passes
    {
        size_t tot = (size_t)BATCH*LL*LL;
        k_fuse1<<<(unsigned)((tot + 255)/256), 256>>>();
        k_fuse2<<<(unsigned)((tot + 255)/256), 256>>>();
    }
    // 8. softmax over patches (in place in g_A)
    k_softmax<<<dim3(LL/256, BATCH), 256>>>();
    // 9. raw 4x4 patches
    k_buildR<<<(BATCH*LL*PDIM + 255)/256, 256>>>(b);
    // 10. deconv GEMM: g_OC[p, ab] = sum_l R[l,p] * S[l,ab]   [1024 x 2304, K=2304]
    k_gemm<false,false><<<dim3(LL/128, PDIM/128, BATCH), 256>>>(
        pR, pA, pOC, nullptr,
        PDIM, LL, LL, PDIM, LL,
        (size_t)LL*PDIM, (size_t)LL*LL, (size_t)PDIM*LL, 0);
    // 11. col2im (/4)
    k_col2im<<<(BATCH*CH*H*W + 255)/256, 256>>>();
    // 12-13. final convs
    k_conv3x3<<<dim3(6,6,BATCH*8), 256>>>(pY, w1, b1, pT);
    k_conv3x3<<<dim3(6,6,BATCH*8), 256>>>(pT, w2, b2, out);
}

// round 7
// speedup vs baseline: 1.3428x; 1.3428x over previous
#include <cuda_runtime.h>
#include <cuda_bf16.h>
#include <math.h>
#include <stdint.h>

#define BATCH 4
#define CH    64
#define H     96
#define W     96
#define HD    48          // downsampled H/W
#define LL    2304        // 48*48 patches
#define KC    576         // CH*9
#define PDIM  1024        // CH*16

// ---------------- scratch (device globals; no cudaMalloc allowed) ----------------
__device__ float          g_fd [BATCH*CH*HD*HD];
__device__ float          g_bd [BATCH*CH*HD*HD];
__device__ __nv_bfloat16  g_Gh [BATCH*LL*KC];
__device__ __nv_bfloat16  g_Gl [BATCH*LL*KC];
__device__ __nv_bfloat16  g_Fh [BATCH*LL*KC];
__device__ __nv_bfloat16  g_Fl [BATCH*LL*KC];
__device__ float          g_inv[BATCH*LL];
__device__ float          g_A  [BATCH*(size_t)LL*LL];   // score / softmax buffer
__device__ float          g_Bf [BATCH*(size_t)LL*LL];   // fuse ping-pong
__device__ __nv_bfloat16  g_RTh[BATCH*(size_t)PDIM*LL]; // R transposed [p][l]
__device__ __nv_bfloat16  g_RTl[BATCH*(size_t)PDIM*LL];
__device__ __nv_bfloat16  g_WTh[BATCH*(size_t)LL*LL];   // softmax transposed [fp][l]
__device__ __nv_bfloat16  g_WTl[BATCH*(size_t)LL*LL];
__device__ float          g_OC [BATCH*(size_t)PDIM*LL];
__device__ float          g_y  [BATCH*CH*H*W];
__device__ float          g_t  [BATCH*CH*H*W];

// =====================  mma.sync helpers (generic PTX, sm_80+)  =====================
__device__ __forceinline__ uint32_t smem_u32(const void* p) {
    uint32_t a;
    asm("{ .reg .u64 t; cvta.to.shared.u64 t, %1; cvt.u32.u64 %0, t; }" : "=r"(a) : "l"(p));
    return a;
}
__device__ __forceinline__ void ldmA(uint32_t* a, uint32_t addr) {
    asm volatile("ldmatrix.sync.aligned.m8n8.x4.shared.b16 {%0,%1,%2,%3}, [%4];"
                 : "=r"(a[0]), "=r"(a[1]), "=r"(a[2]), "=r"(a[3]) : "r"(addr));
}
// B tile is [n][k] row-major == mathematical col-major B -> NON-transposed ldmatrix
__device__ __forceinline__ void ldmB(uint32_t* b, uint32_t addr) {
    asm volatile("ldmatrix.sync.aligned.m8n8.x2.shared.b16 {%0,%1}, [%2];"
                 : "=r"(b[0]), "=r"(b[1]) : "r"(addr));
}
__device__ __forceinline__ void mma_bf16(float* d, const uint32_t* a, const uint32_t* b) {
    asm volatile("mma.sync.aligned.m16n8k16.row.col.f32.bf16.bf16.f32 "
                 "{%0,%1,%2,%3}, {%4,%5,%6,%7}, {%8,%9}, {%0,%1,%2,%3};"
                 : "+f"(d[0]), "+f"(d[1]), "+f"(d[2]), "+f"(d[3])
                 : "r"(a[0]), "r"(a[1]), "r"(a[2]), "r"(a[3]), "r"(b[0]), "r"(b[1]));
}

// =====================  element-wise / producer kernels  =====================

__global__ void k_downsample(const float* __restrict__ f, const float* __restrict__ b) {
    int idx = blockIdx.x*blockDim.x + threadIdx.x;
    if (idx >= BATCH*CH*HD*HD) return;
    int w = idx % HD, h = (idx/HD)%HD, c = (idx/(HD*HD))%CH, bi = idx/(CH*HD*HD);
    int src = ((bi*CH + c)*H + 2*h)*W + 2*w;
    g_fd[idx] = f[src];
    g_bd[idx] = b[src];
}

// G[l][c*9+ij]: scrambled 3x3 bd patches (K-major), bf16 hi/lo split
__global__ void k_buildG() {
    int idx = blockIdx.x*blockDim.x + threadIdx.x;
    if (idx >= BATCH*LL*KC) return;
    int k  = idx % KC;
    int l  = (idx / KC) % LL;
    int bi = idx / (KC*LL);
    int c  = k / 9;  int ij = k % 9;  int i = ij/3, j = ij%3;
    int c0 = l / 36;
    int p0 = (l % 36)*64 + c;
    int h0 = p0 / 48, w0 = p0 % 48;
    int hh = h0 + i - 1, ww = w0 + j - 1;
    float v = 0.f;
    if ((unsigned)hh < HD && (unsigned)ww < HD)
        v = g_bd[((bi*CH + c0)*HD + hh)*HD + ww];
    __nv_bfloat16 hv = __float2bfloat16(v);
    g_Gh[idx] = hv;
    g_Gl[idx] = __float2bfloat16(v - __bfloat162float(hv));
}

// F[fp][c*9+ij]: fd im2col (pad 1) (K-major), bf16 hi/lo split
__global__ void k_buildF() {
    int idx = blockIdx.x*blockDim.x + threadIdx.x;
    if (idx >= BATCH*LL*KC) return;
    int k  = idx % KC;
    int fp = (idx / KC) % LL;
    int bi = idx / (KC*LL);
    int c  = k / 9;  int ij = k % 9;  int i = ij/3, j = ij%3;
    int fh = fp / 48, fw = fp % 48;
    int hh = fh + i - 1, ww = fw + j - 1;
    float v = 0.f;
    if ((unsigned)hh < HD && (unsigned)ww < HD)
        v = g_fd[((bi*CH + c)*HD + hh)*HD + ww];
    __nv_bfloat16 hv = __float2bfloat16(v);
    g_Fh[idx] = hv;
    g_Fl[idx] = __float2bfloat16(v - __bfloat162float(hv));
}

// per-row inverse norm of G (reconstructed hi+lo)
__global__ void k_norm() {
    int l  = blockIdx.x;
    int bi = blockIdx.y;
    const __nv_bfloat16* rh = g_Gh + ((size_t)bi*LL + l)*KC;
    const __nv_bfloat16* rl = g_Gl + ((size_t)bi*LL + l)*KC;
    float s = 0.f;
    for (int k = threadIdx.x; k < KC; k += 128) {
        float v = __bfloat162float(rh[k]) + __bfloat162float(rl[k]);
        s += v*v;
    }
    #pragma unroll
    for (int off = 16; off > 0; off >>= 1) s += __shfl_down_sync(0xffffffffu, s, off);
    __shared__ float red[4];
    if ((threadIdx.x & 31) == 0) red[threadIdx.x >> 5] = s;
    __syncthreads();
    if (threadIdx.x == 0) {
        float t = red[0]+red[1]+red[2]+red[3];
        float n = sqrtf(t);
        g_inv[(size_t)bi*LL + l] = 1.0f / fmaxf(n, 1e-4f);
    }
}

// R_T[p][l]: scrambled 4x4 stride-2 raw b patches, transposed layout (K-major in l)
__global__ void k_buildR(const float* __restrict__ bfull) {
    size_t idx = (size_t)blockIdx.x*blockDim.x + threadIdx.x;
    if (idx >= (size_t)BATCH*PDIM*LL) return;
    int l  = (int)(idx % LL);
    int p  = (int)((idx / LL) % PDIM);
    int bi = (int)(idx / ((size_t)PDIM*LL));
    int o  = p >> 4;  int ij = p & 15;  int i = ij >> 2, j = ij & 3;
    int c0 = l / 36;
    int p0 = (l % 36)*64 + o;
    int h0 = p0 / 48, w0 = p0 % 48;
    int hy = 2*h0 + i - 1, hx = 2*w0 + j - 1;
    float v = 0.f;
    if ((unsigned)hy < H && (unsigned)hx < W)
        v = bfull[((bi*CH + c0)*H + hy)*W + hx];
    __nv_bfloat16 hv = __float2bfloat16(v);
    g_RTh[idx] = hv;
    g_RTl[idx] = __float2bfloat16(v - __bfloat162float(hv));
}

// =====================  bf16-split tensor-core GEMM (mma.sync)  =====================
// C[m,n] = rowScale[m] * sum_k (Ah+Al)[m,k]*(Bh+Bl)[n,k]   (lo*lo dropped)
// A,B K-major, leading dim == K. Block tile 128x128, K-chunk 32, 8 warps (2x4).
#define APAD 40   // bf16 units per smem row (80B: 16B-aligned, conflict-free ldmatrix)

__global__ void __launch_bounds__(256)
k_mma(const __nv_bfloat16* __restrict__ Ah, const __nv_bfloat16* __restrict__ Al,
      const __nv_bfloat16* __restrict__ Bh, const __nv_bfloat16* __restrict__ Bl,
      float* __restrict__ C, const float* __restrict__ rowScale,
      int K, int N, size_t sA, size_t sB, size_t sC, int scaleStride)
{
    __shared__ __nv_bfloat16 sAh[128*APAD], sAl[128*APAD];
    __shared__ __nv_bfloat16 sBh[128*APAD], sBl[128*APAD];
    const int bi = blockIdx.z;
    Ah += (size_t)bi*sA;  Al += (size_t)bi*sA;
    Bh += (size_t)bi*sB;  Bl += (size_t)bi*sB;
    C  += (size_t)bi*sC;
    const int m0 = blockIdx.y*128, n0 = blockIdx.x*128;
    const int tid = threadIdx.x, lane = tid & 31, wid = tid >> 5;
    const int wm = wid & 1, wn = wid >> 1;     // 2 x 4 warp grid; warp tile 64x32
    const uint32_t uAh = smem_u32(sAh), uAl = smem_u32(sAl);
    const uint32_t uBh = smem_u32(sBh), uBl = smem_u32(sBl);

    float acc[4][4][4];
    #pragma unroll
    for (int mi=0; mi<4; mi++)
        #pragma unroll
        for (int ni=0; ni<4; ni++)
            #pragma unroll
            for (int q=0; q<4; q++)
                acc[mi][ni][q] = 0.f;

    for (int k0 = 0; k0 < K; k0 += 32) {
        // load 4 operand tiles (128 x 32 bf16 each); each thread: 2 uint4 per operand
        #pragma unroll
        for (int it = 0; it < 2; it++) {
            int i = tid + it*256;
            int r = i >> 2, c4 = i & 3;
            size_t gA = (size_t)(m0 + r)*K + k0 + c4*8;
            size_t gB = (size_t)(n0 + r)*K + k0 + c4*8;
            int d = r*APAD + c4*8;
            *(uint4*)(sAh + d) = *(const uint4*)(Ah + gA);
            *(uint4*)(sAl + d) = *(const uint4*)(Al + gA);
            *(uint4*)(sBh + d) = *(const uint4*)(Bh + gB);
            *(uint4*)(sBl + d) = *(const uint4*)(Bl + gB);
        }
        __syncthreads();
        #pragma unroll
        for (int kk = 0; kk < 2; kk++) {
            uint32_t fAh[4][4], fAl[4][4], fBh[4][2], fBl[4][2];
            #pragma unroll
            for (int mi = 0; mi < 4; mi++) {
                int row = wm*64 + mi*16 + (lane & 15);
                int col = kk*16 + (lane >> 4)*8;
                uint32_t ad = (uint32_t)(row*APAD + col)*2;
                ldmA(fAh[mi], uAh + ad);
                ldmA(fAl[mi], uAl + ad);
            }
            #pragma unroll
            for (int ni = 0; ni < 4; ni++) {
                int row = wn*32 + ni*8 + (lane & 7);
                int col = kk*16 + ((lane >> 3) & 1)*8;
                uint32_t ad = (uint32_t)(row*APAD + col)*2;
                ldmB(fBh[ni], uBh + ad);
                ldmB(fBl[ni], uBl + ad);
            }
            #pragma unroll
            for (int mi = 0; mi < 4; mi++)
                #pragma unroll
                for (int ni = 0; ni < 4; ni++) {
                    mma_bf16(acc[mi][ni], fAh[mi], fBh[ni]);
                    mma_bf16(acc[mi][ni], fAh[mi], fBl[ni]);
                    mma_bf16(acc[mi][ni], fAl[mi], fBh[ni]);
                }
        }
        __syncthreads();
    }

    // epilogue
    const int r0 = lane >> 2, c0 = (lane & 3)*2;
    #pragma unroll
    for (int mi = 0; mi < 4; mi++) {
        int m = m0 + wm*64 + mi*16;
        float s1 = 1.f, s2 = 1.f;
        if (rowScale) {
            s1 = rowScale[(size_t)bi*scaleStride + m + r0];
            s2 = rowScale[(size_t)bi*scaleStride + m + r0 + 8];
        }
        #pragma unroll
        for (int ni = 0; ni < 4; ni++) {
            int n = n0 + wn*32 + ni*8 + c0;
            float2 v1 = make_float2(acc[mi][ni][0]*s1, acc[mi][ni][1]*s1);
            float2 v2 = make_float2(acc[mi][ni][2]*s2, acc[mi][ni][3]*s2);
            *(float2*)&C[(size_t)(m + r0    )*N + n] = v1;
            *(float2*)&C[(size_t)(m + r0 + 8)*N + n] = v2;
        }
    }
}

// =====================  fuse / softmax / transpose  =====================

__global__ void k_fuse1() {
    size_t idx = (size_t)blockIdx.x*blockDim.x + threadIdx.x;
    if (idx >= (size_t)BATCH*LL*LL) return;
    int fp = (int)(idx % LL);
    int l  = (int)((idx / LL) % LL);
    int bi = (int)(idx / ((size_t)LL*LL));
    const float* src = g_A + (size_t)bi*LL*LL;
    float s = 0.f;
    #pragma unroll
    for (int d=-1; d<=1; d++) {
        int l2 = l+d, f2 = fp+d;
        if ((unsigned)l2 < LL && (unsigned)f2 < LL)
            s += src[(size_t)l2*LL + f2];
    }
    g_Bf[idx] = s;
}

__global__ void k_fuse2() {
    size_t idx = (size_t)blockIdx.x*blockDim.x + threadIdx.x;
    if (idx >= (size_t)BATCH*LL*LL) return;
    int fp = (int)(idx % LL);
    int l  = (int)((idx / LL) % LL);
    int bi = (int)(idx / ((size_t)LL*LL));
    const float* src = g_Bf + (size_t)bi*LL*LL;
    int r = (l  % 48)*48 + l /48;
    int q = (fp % 48)*48 + fp/48;
    float s = 0.f;
    #pragma unroll
    for (int d=-1; d<=1; d++) {
        int r2 = r+d, q2 = q+d;
        if ((unsigned)r2 < LL && (unsigned)q2 < LL) {
            int l2 = (r2 % 48)*48 + r2/48;
            int f2 = (q2 % 48)*48 + q2/48;
            s += src[(size_t)l2*LL + f2];
        }
    }
    g_A[idx] = s;
}

// column softmax over l, scale 10, in-place g_A
__global__ void k_softmax() {
    int bi = blockIdx.y;
    int fp = blockIdx.x*256 + threadIdx.x;
    float* base = g_A + (size_t)bi*LL*LL + fp;
    float mx = -1e30f;
    for (int l=0; l<LL; l++) mx = fmaxf(mx, base[(size_t)l*LL]);
    float sum = 0.f;
    for (int l=0; l<LL; l++) sum += expf(10.0f*(base[(size_t)l*LL]-mx));
    float inv = 1.0f/sum;
    for (int l=0; l<LL; l++) {
        float v = expf(10.0f*(base[(size_t)l*LL]-mx))*inv;
        base[(size_t)l*LL] = v;
    }
}

// WT[fp][l] = W[l][fp]  (plain matrix transpose) -> bf16 hi/lo
__global__ void k_transW() {
    __shared__ float tile[32][33];
    int bi = blockIdx.z;
    int l0 = blockIdx.y*32, f0 = blockIdx.x*32;
    int tx = threadIdx.x, ty = threadIdx.y;
    const float* src = g_A + (size_t)bi*LL*LL;
    #pragma unroll
    for (int i = 0; i < 32; i += 8)
        tile[ty+i][tx] = src[(size_t)(l0+ty+i)*LL + f0+tx];
    __syncthreads();
    size_t obase = (size_t)bi*LL*LL;
    #pragma unroll
    for (int i = 0; i < 32; i += 8) {
        float v = tile[tx][ty+i];
        size_t o = obase + (size_t)(f0+ty+i)*LL + l0 + tx;
        __nv_bfloat16 h = __float2bfloat16(v);
        g_WTh[o] = h;
        g_WTl[o] = __float2bfloat16(v - __bfloat162float(h));
    }
}

// =====================  col2im + convs  =====================

__global__ void k_col2im() {
    int idx = blockIdx.x*blockDim.x + threadIdx.x;
    if (idx >= BATCH*CH*H*W) return;
    int x  = idx % W;
    int y  = (idx / W) % H;
    int o  = (idx / (H*W)) % CH;
    int bi = idx / (CH*H*W);
    const float* OC = g_OC + (size_t)bi*PDIM*LL;
    float s = 0.f;
    int i0 = (y+1)&1, j0 = (x+1)&1;
    #pragma unroll
    for (int di=0; di<2; di++) {
        int i = i0 + 2*di;
        int a = (y+1-i)/2;
        if ((unsigned)a >= 48u) continue;
        #pragma unroll
        for (int dj=0; dj<2; dj++) {
            int j = j0 + 2*dj;
            int bb = (x+1-j)/2;
            if ((unsigned)bb >= 48u) continue;
            s += OC[(size_t)(o*16 + i*4 + j)*LL + a*48 + bb];
        }
    }
    g_y[idx] = 0.25f*s;
}

__global__ void __launch_bounds__(256)
k_conv3x3(const float* __restrict__ in, const float* __restrict__ wgt,
          const float* __restrict__ bias, float* __restrict__ out)
{
    int bi = blockIdx.z >> 3, og = blockIdx.z & 7;
    int x0 = blockIdx.x * 16, y0 = blockIdx.y * 16;
    int tid = threadIdx.x;
    int tx = tid & 15, ty = tid >> 4;
    __shared__ float sIn[8][18][18];
    __shared__ float sW[8][9][8];
    float acc[8];
    #pragma unroll
    for (int o=0;o<8;o++) acc[o]=0.f;

    for (int cb = 0; cb < CH; cb += 8) {
        for (int lin = tid; lin < 8*18*18; lin += 256) {
            int c = lin / 324; int rem = lin % 324;
            int iy = rem / 18, ix = rem % 18;
            int gy = y0 + iy - 1, gx = x0 + ix - 1;
            float v = 0.f;
            if ((unsigned)gy < H && (unsigned)gx < W)
                v = in[(((size_t)bi*CH + cb + c)*H + gy)*W + gx];
            sIn[c][iy][ix] = v;
        }
        for (int lin = tid; lin < 576; lin += 256) {
            int c = lin / 72; int rem = lin % 72;
            int ij = rem / 8, o = rem % 8;
            sW[c][ij][o] = wgt[((og*8+o)*CH + cb + c)*9 + ij];
        }
        __syncthreads();
        #pragma unroll
        for (int c=0;c<8;c++)
            #pragma unroll
            for (int dy=0;dy<3;dy++)
                #pragma unroll
                for (int dx=0;dx<3;dx++) {
                    float v = sIn[c][ty+dy][tx+dx];
                    const float* wp = &sW[c][dy*3+dx][0];
                    #pragma unroll
                    for (int o=0;o<8;o++) acc[o] += v * wp[o];
                }
        __syncthreads();
    }
    #pragma unroll
    for (int o=0;o<8;o++)
        out[(((size_t)bi*CH + og*8 + o)*H + y0+ty)*W + x0+tx] = acc[o] + bias[og*8+o];
}

// =====================  host launcher  =====================
extern "C" void kernel_launch(void* const* d_in, const int* in_sizes, int n_in,
                              void* d_out, int out_size) {
    const float* f  = (const float*)d_in[0];
    const float* b  = (const float*)d_in[1];
    const float* w1 = (const float*)d_in[2];
    const float* b1 = (const float*)d_in[3];
    const float* w2 = (const float*)d_in[4];
    const float* b2 = (const float*)d_in[5];
    float* out = (float*)d_out;

    __nv_bfloat16 *pGh, *pGl, *pFh, *pFl, *pRTh, *pRTl, *pWTh, *pWTl;
    float *pInv, *pA, *pOC, *pY, *pT;
    cudaGetSymbolAddress((void**)&pGh,  g_Gh);
    cudaGetSymbolAddress((void**)&pGl,  g_Gl);
    cudaGetSymbolAddress((void**)&pFh,  g_Fh);
    cudaGetSymbolAddress((void**)&pFl,  g_Fl);
    cudaGetSymbolAddress((void**)&pRTh, g_RTh);
    cudaGetSymbolAddress((void**)&pRTl, g_RTl);
    cudaGetSymbolAddress((void**)&pWTh, g_WTh);
    cudaGetSymbolAddress((void**)&pWTl, g_WTl);
    cudaGetSymbolAddress((void**)&pInv, g_inv);
    cudaGetSymbolAddress((void**)&pA,   g_A);
    cudaGetSymbolAddress((void**)&pOC,  g_OC);
    cudaGetSymbolAddress((void**)&pY,   g_y);
    cudaGetSymbolAddress((void**)&pT,   g_t);

    // 1. downsample
    k_downsample<<<(BATCH*CH*HD*HD + 255)/256, 256>>>(f, b);
    // 2-3. build split-bf16 matrices
    k_buildG<<<(BATCH*LL*KC + 255)/256, 256>>>();
    k_buildF<<<(BATCH*LL*KC + 255)/256, 256>>>();
    // 4. norms
    k_norm<<<dim3(LL, BATCH), 128>>>();
    // 5. correlation GEMM (HMMA bf16-split): g_A[l][fp] = inv[l]*(G·F^T), M=N=2304, K=576
    k_mma<<<dim3(LL/128, LL/128, BATCH), 256>>>(
        pGh, pGl, pFh, pFl, pA, pInv,
        KC, LL, (size_t)LL*KC, (size_t)LL*KC, (size_t)LL*LL, LL);
    // 6-7. fuse passes
    {
        size_t tot = (size_t)BATCH*LL*LL;
        k_fuse1<<<(unsigned)((tot + 255)/256), 256>>>();
        k_fuse2<<<(unsigned)((tot + 255)/256), 256>>>();
    }
    // 8. softmax (in place)
    k_softmax<<<dim3(LL/256, BATCH), 256>>>();
    // 9a. transpose softmax -> WT (bf16 split)
    k_transW<<<dim3(LL/32, LL/32, BATCH), dim3(32,8)>>>();
    // 9b. raw 4x4 patches, transposed (bf16 split)
    {
        size_t tot = (size_t)BATCH*PDIM*LL;
        k_buildR<<<(unsigned)((tot + 255)/256), 256>>>(b);
    }
    // 10. deconv GEMM (HMMA bf16-split): g_OC[p][ab] = R_T·WT^T, M=1024, N=2304, K=2304
    k_mma<<<dim3(LL/128, PDIM/128, BATCH), 256>>>(
        pRTh, pRTl, pWTh, pWTl, pOC, nullptr,
        LL, LL, (size_t)PDIM*LL, (size_t)LL*LL, (size_t)PDIM*LL, 0);
    // 11. col2im (/4)
    k_col2im<<<(BATCH*CH*H*W + 255)/256, 256>>>();
    // 12-13. final convs
    k_conv3x3<<<dim3(6,6,BATCH*8), 256>>>(pY, w1, b1, pT);
    k_conv3x3<<<dim3(6,6,BATCH*8), 256>>>(pT, w2, b2, out);
}

// round 9
// speedup vs baseline: 1.5062x; 1.1216x over previous
#include <cuda_runtime.h>
#include <cuda_bf16.h>
#include <math.h>
#include <stdint.h>

#define BATCH 4
#define CH    64
#define H     96
#define W     96
#define HD    48          // downsampled H/W
#define LL    2304        // 48*48 patches
#define KC    576         // CH*9
#define PDIM  1024        // CH*16

// t(x) = (x%48)*48 + x/48  -- involutive index permutation (48x48 transpose)
__device__ __forceinline__ int permt(int x) { return (x % 48)*48 + x/48; }

// ---------------- scratch (device globals; no cudaMalloc allowed) ----------------
__device__ float          g_fd [BATCH*CH*HD*HD];
__device__ float          g_bd [BATCH*CH*HD*HD];
__device__ __nv_bfloat16  g_Gh [BATCH*LL*KC];
__device__ __nv_bfloat16  g_Gl [BATCH*LL*KC];
__device__ __nv_bfloat16  g_Fh [BATCH*LL*KC];
__device__ __nv_bfloat16  g_Fl [BATCH*LL*KC];
__device__ float          g_inv[BATCH*LL];
__device__ float          g_A  [BATCH*(size_t)LL*LL];   // score / permuted / softmax buffer
__device__ float          g_Bf [BATCH*(size_t)LL*LL];   // fuse ping-pong
__device__ __nv_bfloat16  g_RTh[BATCH*(size_t)PDIM*LL]; // R permuted-transposed [p][r]
__device__ __nv_bfloat16  g_RTl[BATCH*(size_t)PDIM*LL];
__device__ __nv_bfloat16  g_WTh[BATCH*(size_t)LL*LL];   // softmax transposed+unpermuted [ab][r]
__device__ __nv_bfloat16  g_WTl[BATCH*(size_t)LL*LL];
__device__ float          g_OC [BATCH*(size_t)PDIM*LL];
__device__ float          g_y  [BATCH*CH*H*W];
__device__ float          g_t  [BATCH*CH*H*W];

// =====================  mma.sync / cp.async helpers (generic PTX, sm_80+)  ============
__device__ __forceinline__ uint32_t smem_u32(const void* p) {
    uint32_t a;
    asm("{ .reg .u64 t; cvta.to.shared.u64 t, %1; cvt.u32.u64 %0, t; }" : "=r"(a) : "l"(p));
    return a;
}
__device__ __forceinline__ void ldmA(uint32_t* a, uint32_t addr) {
    asm volatile("ldmatrix.sync.aligned.m8n8.x4.shared.b16 {%0,%1,%2,%3}, [%4];"
                 : "=r"(a[0]), "=r"(a[1]), "=r"(a[2]), "=r"(a[3]) : "r"(addr));
}
__device__ __forceinline__ void ldmB(uint32_t* b, uint32_t addr) {
    asm volatile("ldmatrix.sync.aligned.m8n8.x2.shared.b16 {%0,%1}, [%2];"
                 : "=r"(b[0]), "=r"(b[1]) : "r"(addr));
}
__device__ __forceinline__ void mma_bf16(float* d, const uint32_t* a, const uint32_t* b) {
    asm volatile("mma.sync.aligned.m16n8k16.row.col.f32.bf16.bf16.f32 "
                 "{%0,%1,%2,%3}, {%4,%5,%6,%7}, {%8,%9}, {%0,%1,%2,%3};"
                 : "+f"(d[0]), "+f"(d[1]), "+f"(d[2]), "+f"(d[3])
                 : "r"(a[0]), "r"(a[1]), "r"(a[2]), "r"(a[3]), "r"(b[0]), "r"(b[1]));
}
__device__ __forceinline__ void cp16(uint32_t dst, const void* src) {
    asm volatile("cp.async.cg.shared.global [%0], [%1], 16;" :: "r"(dst), "l"(src));
}
#define CP_COMMIT() asm volatile("cp.async.commit_group;" ::: "memory")
#define CP_WAIT(n)  asm volatile("cp.async.wait_group %0;" :: "n"(n) : "memory")

// =====================  element-wise / producer kernels  =====================

__global__ void k_downsample(const float* __restrict__ f, const float* __restrict__ b) {
    int idx = blockIdx.x*blockDim.x + threadIdx.x;
    if (idx >= BATCH*CH*HD*HD) return;
    int w = idx % HD, h = (idx/HD)%HD, c = (idx/(HD*HD))%CH, bi = idx/(CH*HD*HD);
    int src = ((bi*CH + c)*H + 2*h)*W + 2*w;
    g_fd[idx] = f[src];
    g_bd[idx] = b[src];
}

// G[l][c*9+ij]: scrambled 3x3 bd patches (K-major), bf16 hi/lo split
__global__ void k_buildG() {
    int idx = blockIdx.x*blockDim.x + threadIdx.x;
    if (idx >= BATCH*LL*KC) return;
    int k  = idx % KC;
    int l  = (idx / KC) % LL;
    int bi = idx / (KC*LL);
    int c  = k / 9;  int ij = k % 9;  int i = ij/3, j = ij%3;
    int c0 = l / 36;
    int p0 = (l % 36)*64 + c;
    int h0 = p0 / 48, w0 = p0 % 48;
    int hh = h0 + i - 1, ww = w0 + j - 1;
    float v = 0.f;
    if ((unsigned)hh < HD && (unsigned)ww < HD)
        v = g_bd[((bi*CH + c0)*HD + hh)*HD + ww];
    __nv_bfloat16 hv = __float2bfloat16(v);
    g_Gh[idx] = hv;
    g_Gl[idx] = __float2bfloat16(v - __bfloat162float(hv));
}

// F[fp][c*9+ij]: fd im2col (pad 1) (K-major), bf16 hi/lo split
__global__ void k_buildF() {
    int idx = blockIdx.x*blockDim.x + threadIdx.x;
    if (idx >= BATCH*LL*KC) return;
    int k  = idx % KC;
    int fp = (idx / KC) % LL;
    int bi = idx / (KC*LL);
    int c  = k / 9;  int ij = k % 9;  int i = ij/3, j = ij%3;
    int fh = fp / 48, fw = fp % 48;
    int hh = fh + i - 1, ww = fw + j - 1;
    float v = 0.f;
    if ((unsigned)hh < HD && (unsigned)ww < HD)
        v = g_fd[((bi*CH + c)*HD + hh)*HD + ww];
    __nv_bfloat16 hv = __float2bfloat16(v);
    g_Fh[idx] = hv;
    g_Fl[idx] = __float2bfloat16(v - __bfloat162float(hv));
}

// per-row inverse norm of G (reconstructed hi+lo)
__global__ void k_norm() {
    int l  = blockIdx.x;
    int bi = blockIdx.y;
    const __nv_bfloat16* rh = g_Gh + ((size_t)bi*LL + l)*KC;
    const __nv_bfloat16* rl = g_Gl + ((size_t)bi*LL + l)*KC;
    float s = 0.f;
    for (int k = threadIdx.x; k < KC; k += 128) {
        float v = __bfloat162float(rh[k]) + __bfloat162float(rl[k]);
        s += v*v;
    }
    #pragma unroll
    for (int off = 16; off > 0; off >>= 1) s += __shfl_down_sync(0xffffffffu, s, off);
    __shared__ float red[4];
    if ((threadIdx.x & 31) == 0) red[threadIdx.x >> 5] = s;
    __syncthreads();
    if (threadIdx.x == 0) {
        float t = red[0]+red[1]+red[2]+red[3];
        float n = sqrtf(t);
        g_inv[(size_t)bi*LL + l] = 1.0f / fmaxf(n, 1e-4f);
    }
}

// Rp_T[p][r] = R[t(r)][p]: scrambled 4x4 stride-2 raw b patches, row-permuted + transposed
__global__ void k_buildR(const float* __restrict__ bfull) {
    size_t idx = (size_t)blockIdx.x*blockDim.x + threadIdx.x;
    if (idx >= (size_t)BATCH*PDIM*LL) return;
    int r  = (int)(idx % LL);
    int p  = (int)((idx / LL) % PDIM);
    int bi = (int)(idx / ((size_t)PDIM*LL));
    int l  = permt(r);
    int o  = p >> 4;  int ij = p & 15;  int i = ij >> 2, j = ij & 3;
    int c0 = l / 36;
    int p0 = (l % 36)*64 + o;
    int h0 = p0 / 48, w0 = p0 % 48;
    int hy = 2*h0 + i - 1, hx = 2*w0 + j - 1;
    float v = 0.f;
    if ((unsigned)hy < H && (unsigned)hx < W)
        v = bfull[((bi*CH + c0)*H + hy)*W + hx];
    __nv_bfloat16 hv = __float2bfloat16(v);
    g_RTh[idx] = hv;
    g_RTl[idx] = __float2bfloat16(v - __bfloat162float(hv));
}

// =====================  bf16-split tensor-core GEMM (mma.sync + cp.async x2)  =========
// C[m,n] = rowScale[m] * sum_k (Ah+Al)[m,k]*(Bh+Bl)[n,k]   (lo*lo dropped)
// A,B K-major, leading dim == K. Block tile 128x128, K-chunk 32, 8 warps (2x4),
// 2-stage cp.async pipeline in dynamic smem.
#define APADB   80          // bytes per smem row (40 bf16: conflict-free ldmatrix)
#define TILEB   (128*APADB) // 10240 bytes per operand tile
#define STAGEB  (4*TILEB)   // 40960 bytes per stage
#define GSMEM   (2*STAGEB)  // 81920 bytes total

__global__ void __launch_bounds__(256)
k_mma(const __nv_bfloat16* __restrict__ Ah, const __nv_bfloat16* __restrict__ Al,
      const __nv_bfloat16* __restrict__ Bh, const __nv_bfloat16* __restrict__ Bl,
      float* __restrict__ C, const float* __restrict__ rowScale,
      int K, int N, size_t sA, size_t sB, size_t sC, int scaleStride)
{
    extern __shared__ __align__(16) char smem[];
    const int bi = blockIdx.z;
    Ah += (size_t)bi*sA;  Al += (size_t)bi*sA;
    Bh += (size_t)bi*sB;  Bl += (size_t)bi*sB;
    C  += (size_t)bi*sC;
    const int m0 = blockIdx.y*128, n0 = blockIdx.x*128;
    const int tid = threadIdx.x, lane = tid & 31, wid = tid >> 5;
    const int wm = wid & 1, wn = wid >> 1;     // 2 x 4 warp grid; warp tile 64x32
    const uint32_t ub = smem_u32(smem);

    float acc[4][4][4];
    #pragma unroll
    for (int mi=0; mi<4; mi++)
        #pragma unroll
        for (int ni=0; ni<4; ni++)
            #pragma unroll
            for (int q=0; q<4; q++)
                acc[mi][ni][q] = 0.f;

    const int nck = K >> 5;

    // per-thread load slots: 2 rows x (16B each operand)
    const int lr0 = tid >> 2, lc = (tid & 3)*16;        // row, byte-col (0..48)
    // issue chunk ck into stage st
    auto load_chunk = [&](int ck, int st) {
        int k0 = ck << 5;
        uint32_t base = ub + st*STAGEB;
        #pragma unroll
        for (int it = 0; it < 2; it++) {
            int r = lr0 + it*64;
            uint32_t d = (uint32_t)(r*APADB + lc);
            const __nv_bfloat16* gA = Ah + (size_t)(m0 + r)*K + k0 + lc/2;
            const __nv_bfloat16* gAl = Al + (size_t)(m0 + r)*K + k0 + lc/2;
            const __nv_bfloat16* gB = Bh + (size_t)(n0 + r)*K + k0 + lc/2;
            const __nv_bfloat16* gBl = Bl + (size_t)(n0 + r)*K + k0 + lc/2;
            cp16(base + 0*TILEB + d, gA);
            cp16(base + 1*TILEB + d, gAl);
            cp16(base + 2*TILEB + d, gB);
            cp16(base + 3*TILEB + d, gBl);
        }
    };

    load_chunk(0, 0);
    CP_COMMIT();

    for (int ck = 0; ck < nck; ck++) {
        if (ck + 1 < nck) {
            load_chunk(ck+1, (ck+1)&1);
            CP_COMMIT();
            CP_WAIT(1);
        } else {
            CP_WAIT(0);
        }
        __syncthreads();

        uint32_t base = ub + (ck&1)*STAGEB;
        uint32_t bAh = base, bAl = base + TILEB, bBh = base + 2*TILEB, bBl = base + 3*TILEB;
        #pragma unroll
        for (int kk = 0; kk < 2; kk++) {
            uint32_t fAh[4][4], fAl[4][4], fBh[4][2], fBl[4][2];
            #pragma unroll
            for (int mi = 0; mi < 4; mi++) {
                int row = wm*64 + mi*16 + (lane & 15);
                int colb = kk*32 + (lane >> 4)*16;
                uint32_t ad = (uint32_t)(row*APADB + colb);
                ldmA(fAh[mi], bAh + ad);
                ldmA(fAl[mi], bAl + ad);
            }
            #pragma unroll
            for (int ni = 0; ni < 4; ni++) {
                int row = wn*32 + ni*8 + (lane & 7);
                int colb = kk*32 + ((lane >> 3) & 1)*16;
                uint32_t ad = (uint32_t)(row*APADB + colb);
                ldmB(fBh[ni], bBh + ad);
                ldmB(fBl[ni], bBl + ad);
            }
            #pragma unroll
            for (int mi = 0; mi < 4; mi++)
                #pragma unroll
                for (int ni = 0; ni < 4; ni++) {
                    mma_bf16(acc[mi][ni], fAh[mi], fBh[ni]);
                    mma_bf16(acc[mi][ni], fAh[mi], fBl[ni]);
                    mma_bf16(acc[mi][ni], fAl[mi], fBh[ni]);
                }
        }
        __syncthreads();
    }

    // epilogue
    const int r0 = lane >> 2, c0 = (lane & 3)*2;
    #pragma unroll
    for (int mi = 0; mi < 4; mi++) {
        int m = m0 + wm*64 + mi*16;
        float s1 = 1.f, s2 = 1.f;
        if (rowScale) {
            s1 = rowScale[(size_t)bi*scaleStride + m + r0];
            s2 = rowScale[(size_t)bi*scaleStride + m + r0 + 8];
        }
        #pragma unroll
        for (int ni = 0; ni < 4; ni++) {
            int n = n0 + wn*32 + ni*8 + c0;
            float2 v1 = make_float2(acc[mi][ni][0]*s1, acc[mi][ni][1]*s1);
            float2 v2 = make_float2(acc[mi][ni][2]*s2, acc[mi][ni][3]*s2);
            *(float2*)&C[(size_t)(m + r0    )*N + n] = v1;
            *(float2*)&C[(size_t)(m + r0 + 8)*N + n] = v2;
        }
    }
}

// =====================  fuse (permuted domain) / softmax / transpose  ================

// fuse1 + permutation:  g_Bf[r][q] = sum_d g_A[t(r)+d][t(q)+d]  (flat bounds)
// smem rows stored in padded layout: phys(x) = (x/48)*49 + x%48  (conflict-free stride-48)
__global__ void __launch_bounds__(256) k_fuse1p() {
    __shared__ float rows[3][48*49];
    int r = blockIdx.x, bi = blockIdx.y;
    int tr = permt(r);
    const float* src = g_A + (size_t)bi*LL*LL;
    #pragma unroll
    for (int d = 0; d < 3; d++) {
        int l2 = tr + d - 1;
        if ((unsigned)l2 < LL) {
            const float* sp = src + (size_t)l2*LL;
            for (int i = threadIdx.x; i < LL; i += 256)
                rows[d][(i/48)*49 + (i%48)] = sp[i];
        } else {
            for (int i = threadIdx.x; i < LL; i += 256)
                rows[d][(i/48)*49 + (i%48)] = 0.f;
        }
    }
    __syncthreads();
    float* dst = g_Bf + (size_t)bi*LL*LL + (size_t)r*LL;
    bool up = (tr - 1 >= 0), dn = (tr + 1 < LL);
    for (int q = threadIdx.x; q < LL; q += 256) {
        int tq = permt(q);
        float s = rows[1][(tq/48)*49 + (tq%48)];
        if (up && tq - 1 >= 0) { int x = tq-1; s += rows[0][(x/48)*49 + (x%48)]; }
        if (dn && tq + 1 < LL) { int x = tq+1; s += rows[2][(x/48)*49 + (x%48)]; }
        dst[q] = s;
    }
}

// fuse2 in permuted domain = plain coalesced diagonal 3-tap: g_A = diag3(g_Bf)
__global__ void k_fuse2p() {
    size_t idx = (size_t)blockIdx.x*blockDim.x + threadIdx.x;
    if (idx >= (size_t)BATCH*LL*LL) return;
    int q  = (int)(idx % LL);
    int r  = (int)((idx / LL) % LL);
    int bi = (int)(idx / ((size_t)LL*LL));
    const float* src = g_Bf + (size_t)bi*LL*LL;
    float s = 0.f;
    #pragma unroll
    for (int d=-1; d<=1; d++) {
        int r2 = r+d, q2 = q+d;
        if ((unsigned)r2 < LL && (unsigned)q2 < LL)
            s += src[(size_t)r2*LL + q2];
    }
    g_A[idx] = s;
}

// column softmax over axis-0 (rows), scale 10, in-place g_A (permutation-invariant)
__global__ void k_softmax() {
    int bi = blockIdx.y;
    int fp = blockIdx.x*256 + threadIdx.x;
    float* base = g_A + (size_t)bi*LL*LL + fp;
    float mx = -1e30f;
    for (int l=0; l<LL; l++) mx = fmaxf(mx, base[(size_t)l*LL]);
    float sum = 0.f;
    for (int l=0; l<LL; l++) sum += expf(10.0f*(base[(size_t)l*LL]-mx));
    float inv = 1.0f/sum;
    for (int l=0; l<LL; l++) {
        float v = expf(10.0f*(base[(size_t)l*LL]-mx))*inv;
        base[(size_t)l*LL] = v;
    }
}

// WT[t(q)][r] = Sp[r][q]  (transpose + un-permute columns) -> bf16 hi/lo
__global__ void k_transW() {
    __shared__ float tile[32][33];
    int bi = blockIdx.z;
    int l0 = blockIdx.y*32, f0 = blockIdx.x*32;
    int tx = threadIdx.x, ty = threadIdx.y;
    const float* src = g_A + (size_t)bi*LL*LL;
    #pragma unroll
    for (int i = 0; i < 32; i += 8)
        tile[ty+i][tx] = src[(size_t)(l0+ty+i)*LL + f0+tx];
    __syncthreads();
    size_t obase = (size_t)bi*LL*LL;
    #pragma unroll
    for (int i = 0; i < 32; i += 8) {
        float v = tile[tx][ty+i];
        size_t o = obase + (size_t)permt(f0+ty+i)*LL + l0 + tx;
        __nv_bfloat16 h = __float2bfloat16(v);
        g_WTh[o] = h;
        g_WTl[o] = __float2bfloat16(v - __bfloat162float(h));
    }
}

// =====================  col2im + convs  =====================

__global__ void k_col2im() {
    int idx = blockIdx.x*blockDim.x + threadIdx.x;
    if (idx >= BATCH*CH*H*W) return;
    int x  = idx % W;
    int y  = (idx / W) % H;
    int o  = (idx / (H*W)) % CH;
    int bi = idx / (CH*H*W);
    const float* OC = g_OC + (size_t)bi*PDIM*LL;
    float s = 0.f;
    int i0 = (y+1)&1, j0 = (x+1)&1;
    #pragma unroll
    for (int di=0; di<2; di++) {
        int i = i0 + 2*di;
        int a = (y+1-i)/2;
        if ((unsigned)a >= 48u) continue;
        #pragma unroll
        for (int dj=0; dj<2; dj++) {
            int j = j0 + 2*dj;
            int bb = (x+1-j)/2;
            if ((unsigned)bb >= 48u) continue;
            s += OC[(size_t)(o*16 + i*4 + j)*LL + a*48 + bb];
        }
    }
    g_y[idx] = 0.25f*s;
}

__global__ void __launch_bounds__(256)
k_conv3x3(const float* __restrict__ in, const float* __restrict__ wgt,
          const float* __restrict__ bias, float* __restrict__ out)
{
    int bi = blockIdx.z >> 3, og = blockIdx.z & 7;
    int x0 = blockIdx.x * 16, y0 = blockIdx.y * 16;
    int tid = threadIdx.x;
    int tx = tid & 15, ty = tid >> 4;
    __shared__ float sIn[8][18][18];
    __shared__ float sW[8][9][8];
    float acc[8];
    #pragma unroll
    for (int o=0;o<8;o++) acc[o]=0.f;

    for (int cb = 0; cb < CH; cb += 8) {
        for (int lin = tid; lin < 8*18*18; lin += 256) {
            int c = lin / 324; int rem = lin % 324;
            int iy = rem / 18, ix = rem % 18;
            int gy = y0 + iy - 1, gx = x0 + ix - 1;
            float v = 0.f;
            if ((unsigned)gy < H && (unsigned)gx < W)
                v = in[(((size_t)bi*CH + cb + c)*H + gy)*W + gx];
            sIn[c][iy][ix] = v;
        }
        for (int lin = tid; lin < 576; lin += 256) {
            int c = lin / 72; int rem = lin % 72;
            int ij = rem / 8, o = rem % 8;
            sW[c][ij][o] = wgt[((og*8+o)*CH + cb + c)*9 + ij];
        }
        __syncthreads();
        #pragma unroll
        for (int c=0;c<8;c++)
            #pragma unroll
            for (int dy=0;dy<3;dy++)
                #pragma unroll
                for (int dx=0;dx<3;dx++) {
                    float v = sIn[c][ty+dy][tx+dx];
                    const float* wp = &sW[c][dy*3+dx][0];
                    #pragma unroll
                    for (int o=0;o<8;o++) acc[o] += v * wp[o];
                }
        __syncthreads();
    }
    #pragma unroll
    for (int o=0;o<8;o++)
        out[(((size_t)bi*CH + og*8 + o)*H + y0+ty)*W + x0+tx] = acc[o] + bias[og*8+o];
}

// =====================  host launcher  =====================
extern "C" void kernel_launch(void* const* d_in, const int* in_sizes, int n_in,
                              void* d_out, int out_size) {
    const float* f  = (const float*)d_in[0];
    const float* b  = (const float*)d_in[1];
    const float* w1 = (const float*)d_in[2];
    const float* b1 = (const float*)d_in[3];
    const float* w2 = (const float*)d_in[4];
    const float* b2 = (const float*)d_in[5];
    float* out = (float*)d_out;

    __nv_bfloat16 *pGh, *pGl, *pFh, *pFl, *pRTh, *pRTl, *pWTh, *pWTl;
    float *pInv, *pA, *pOC, *pY, *pT;
    cudaGetSymbolAddress((void**)&pGh,  g_Gh);
    cudaGetSymbolAddress((void**)&pGl,  g_Gl);
    cudaGetSymbolAddress((void**)&pFh,  g_Fh);
    cudaGetSymbolAddress((void**)&pFl,  g_Fl);
    cudaGetSymbolAddress((void**)&pRTh, g_RTh);
    cudaGetSymbolAddress((void**)&pRTl, g_RTl);
    cudaGetSymbolAddress((void**)&pWTh, g_WTh);
    cudaGetSymbolAddress((void**)&pWTl, g_WTl);
    cudaGetSymbolAddress((void**)&pInv, g_inv);
    cudaGetSymbolAddress((void**)&pA,   g_A);
    cudaGetSymbolAddress((void**)&pOC,  g_OC);
    cudaGetSymbolAddress((void**)&pY,   g_y);
    cudaGetSymbolAddress((void**)&pT,   g_t);

    static int smem_set = 0;
    if (!smem_set) {
        cudaFuncSetAttribute(k_mma, cudaFuncAttributeMaxDynamicSharedMemorySize, GSMEM);
        smem_set = 1;
    }

    // 1. downsample
    k_downsample<<<(BATCH*CH*HD*HD + 255)/256, 256>>>(f, b);
    // 2-3. build split-bf16 matrices
    k_buildG<<<(BATCH*LL*KC + 255)/256, 256>>>();
    k_buildF<<<(BATCH*LL*KC + 255)/256, 256>>>();
    // 4. norms
    k_norm<<<dim3(LL, BATCH), 128>>>();
    // 5. correlation GEMM (HMMA bf16-split, cp.async x2): g_A = inv*(G·F^T)
    k_mma<<<dim3(LL/128, LL/128, BATCH), 256, GSMEM>>>(
        pGh, pGl, pFh, pFl, pA, pInv,
        KC, LL, (size_t)LL*KC, (size_t)LL*KC, (size_t)LL*LL, LL);
    // 6. fuse1 + permutation (coalesced)
    k_fuse1p<<<dim3(LL, BATCH), 256>>>();
    // 7. fuse2 in permuted domain (coalesced)
    {
        size_t tot = (size_t)BATCH*LL*LL;
        k_fuse2p<<<(unsigned)((tot + 255)/256), 256>>>();
    }
    // 8. softmax (in place, permuted domain)
    k_softmax<<<dim3(LL/256, BATCH), 256>>>();
    // 9a. transpose + un-permute columns -> WT (bf16 split)
    k_transW<<<dim3(LL/32, LL/32, BATCH), dim3(32,8)>>>();
    // 9b. permuted raw 4x4 patches (bf16 split)
    {
        size_t tot = (size_t)BATCH*PDIM*LL;
        k_buildR<<<(unsigned)((tot + 255)/256), 256>>>(b);
    }
    // 10. deconv GEMM: g_OC[p][ab] = sum_r Rp[r][p]·WT[ab][r]  (output unpermuted)
    k_mma<<<dim3(LL/128, PDIM/128, BATCH), 256, GSMEM>>>(
        pRTh, pRTl, pWTh, pWTl, pOC, nullptr,
        LL, LL, (size_t)PDIM*LL, (size_t)LL*LL, (size_t)PDIM*LL, 0);
    // 11. col2im (/4)
    k_col2im<<<(BATCH*CH*H*W + 255)/256, 256>>>();
    // 12-13. final convs
    k_conv3x3<<<dim3(6,6,BATCH*8), 256>>>(pY, w1, b1, pT);
    k_conv3x3<<<dim3(6,6,BATCH*8), 256>>>(pT, w2, b2, out);
}